// round 14
// baseline (speedup 1.0000x reference)
#include <cuda_runtime.h>
#include <cuda_bf16.h>

// out[i,j,:] = W[d_res] + W[66+d_token] + same_entity*W[132] + W[133+d_chain]
//
// ~98% of pairs are off-chain; their output is one of only 10 vectors
// (d_chain in 0..4  x  same_entity in 0/1). Those 10 vectors live in a 5KB
// smem LUT -> inner loop = LDS.64 (packed feats) + int ops + LDS.128 + STG.128.
// On-chain pairs (~1.6%) read their two W rows from global (L1/L2-resident).
// Smem 13KB, ~32 regs -> 8 CTAs/SM, all 1024 blocks co-resident in one wave.

#define NTHREADS 256
#define NWARPS   8
#define WCOLS4   32      // 128 floats = 32 float4

__device__ __forceinline__ float4 f4add(float4 a, float4 b) {
    return make_float4(a.x + b.x, a.y + b.y, a.z + b.z, a.w + b.w);
}

__global__ __launch_bounds__(NTHREADS)
void relpos_kernel(const float* __restrict__ feats,
                   const float* __restrict__ W,
                   float* __restrict__ out, int n) {
    extern __shared__ float smem[];
    float4* lut    = (float4*)smem;                 // [10][32] float4 = 5KB
    int2*   s_feat = (int2*)(smem + 10 * 128);      // [n] packed feats = 8KB

    const int tid  = threadIdx.x;
    const int lane = tid & 31;
    const int wid  = tid >> 5;
    const float4* W4 = (const float4*)W;

    // ── init: pack feats ─────────────────────────────────────────────
    for (int j = tid; j < n; j += NTHREADS) {
        const float* fj = feats + (size_t)j * 10;
        int res = (int)fj[0], tok = (int)fj[1];
        int asy = (int)fj[2], ent = (int)fj[3], sym = (int)fj[4];
        s_feat[j] = make_int2(asy | (ent << 8) | (sym << 16),
                              res | (tok << 16));
    }

    // ── init: 10-entry off-chain LUT: wbase + W[133+d_ch] + ment*W[132]
    for (int idx = tid; idx < 10 * WCOLS4; idx += NTHREADS) {
        int r = idx >> 5, c = idx & 31;
        int d_ch = r % 5, ment = r / 5;
        float4 v = f4add(__ldg(&W4[65  * WCOLS4 + c]),
                         __ldg(&W4[131 * WCOLS4 + c]));
        v = f4add(v, __ldg(&W4[(133 + d_ch) * WCOLS4 + c]));
        if (ment) v = f4add(v, __ldg(&W4[132 * WCOLS4 + c]));
        lut[idx] = v;
    }

    // on-chain register rows: chain bin 5, with/without entity row
    const float4 wch5  = __ldg(&W4[138 * WCOLS4 + lane]);
    const float4 wch5e = f4add(wch5, __ldg(&W4[132 * WCOLS4 + lane]));
    __syncthreads();

    // ── one block per i-row ──────────────────────────────────────────
    const int  i      = blockIdx.x;
    const int2 pi     = s_feat[i];
    const int  sym_i  = (pi.x >> 16) & 0xFF;
    const int  res_i  = pi.y & 0xFFFF;
    const int  tok_i  = pi.y >> 16;

    float4* outp = (float4*)out + (size_t)i * n * WCOLS4 + lane;

    #pragma unroll 4
    for (int j = wid; j < n; j += NWARPS) {
        const int2 pj = s_feat[j];                     // warp-uniform LDS.64
        const int  x  = pi.x ^ pj.x;
        const bool same  = (x & 0xFF)   == 0;
        const bool mente = (x & 0xFF00) == 0;

        float4 acc;
        if (!same) {                                   // ~98.4%
            int sym_j = (pj.x >> 16) & 0xFF;
            int d_ch  = min(max(sym_i - sym_j + 2, 0), 4);
            int idx   = d_ch + (mente ? 5 : 0);
            acc = lut[idx * WCOLS4 + lane];            // conflict-free LDS.128
        } else {                                       // ~1.6%: W from global
            int dres  = res_i - (pj.y & 0xFFFF);
            int d_res = min(max(dres + 32, 0), 64);
            int d_tok = 65;
            if (dres == 0)
                d_tok = min(max(tok_i - (pj.y >> 16) + 32, 0), 64);
            float4 a = __ldg(&W4[d_res * WCOLS4 + lane]);
            float4 b = __ldg(&W4[(66 + d_tok) * WCOLS4 + lane]);
            acc = f4add(f4add(a, b), mente ? wch5e : wch5);
        }
        outp[(size_t)j * WCOLS4] = acc;
    }
}

extern "C" void kernel_launch(void* const* d_in, const int* in_sizes, int n_in,
                              void* d_out, int out_size) {
    const float* feats = (const float*)d_in[0];
    const float* W     = (const float*)d_in[1];
    float*       out   = (float*)d_out;

    const int n = in_sizes[0] / 10;   // 1024
    const size_t smem = (size_t)10 * 128 * sizeof(float)   // LUT
                      + (size_t)n * sizeof(int2);          // packed feats

    cudaFuncSetAttribute(relpos_kernel,
                         cudaFuncAttributeMaxDynamicSharedMemorySize, (int)smem);

    relpos_kernel<<<n, NTHREADS, smem>>>(feats, W, out, n);
}

// round 17
// speedup vs baseline: 1.0811x; 1.0811x over previous
#include <cuda_runtime.h>
#include <cuda_bf16.h>

// out[i,j,:] = W[d_res] + W[66+d_token] + same_entity*W[132] + W[133+d_chain]
//
// ~98% of pairs are off-chain; their output is one of only 10 vectors
// (d_chain in 0..4  x  same_entity in 0/1) held in a 5KB smem LUT.
// On-chain pairs (~1.6%) read their two W rows from global (L1/L2-resident).
// This round: each warp owns ADJACENT j-pairs -> 1KB contiguous store burst
// per iteration (2x previous spatial locality for the DRAM write scheduler).

#define NTHREADS 256
#define NWARPS   8
#define WCOLS4   32      // 128 floats = 32 float4

__device__ __forceinline__ float4 f4add(float4 a, float4 b) {
    return make_float4(a.x + b.x, a.y + b.y, a.z + b.z, a.w + b.w);
}

__global__ __launch_bounds__(NTHREADS)
void relpos_kernel(const float* __restrict__ feats,
                   const float* __restrict__ W,
                   float* __restrict__ out, int n) {
    extern __shared__ float smem[];
    float4* lut    = (float4*)smem;                 // [10][32] float4 = 5KB
    int2*   s_feat = (int2*)(smem + 10 * 128);      // [n] packed feats = 8KB

    const int tid  = threadIdx.x;
    const int lane = tid & 31;
    const int wid  = tid >> 5;
    const float4* W4 = (const float4*)W;

    // ── init: pack feats ─────────────────────────────────────────────
    for (int j = tid; j < n; j += NTHREADS) {
        const float* fj = feats + (size_t)j * 10;
        int res = (int)fj[0], tok = (int)fj[1];
        int asy = (int)fj[2], ent = (int)fj[3], sym = (int)fj[4];
        s_feat[j] = make_int2(asy | (ent << 8) | (sym << 16),
                              res | (tok << 16));
    }

    // ── init: 10-entry off-chain LUT: wbase + W[133+d_ch] + ment*W[132]
    for (int idx = tid; idx < 10 * WCOLS4; idx += NTHREADS) {
        int r = idx >> 5, c = idx & 31;
        int d_ch = r % 5, ment = r / 5;
        float4 v = f4add(__ldg(&W4[65  * WCOLS4 + c]),
                         __ldg(&W4[131 * WCOLS4 + c]));
        v = f4add(v, __ldg(&W4[(133 + d_ch) * WCOLS4 + c]));
        if (ment) v = f4add(v, __ldg(&W4[132 * WCOLS4 + c]));
        lut[idx] = v;
    }

    // on-chain register rows: chain bin 5, with/without entity row
    const float4 wch5  = __ldg(&W4[138 * WCOLS4 + lane]);
    const float4 wch5e = f4add(wch5, __ldg(&W4[132 * WCOLS4 + lane]));
    __syncthreads();

    // ── one block per i-row ──────────────────────────────────────────
    const int  i      = blockIdx.x;
    const int2 pi     = s_feat[i];
    const int  sym_i  = (pi.x >> 16) & 0xFF;
    const int  res_i  = pi.y & 0xFFFF;
    const int  tok_i  = pi.y >> 16;

    float4* outp = (float4*)out + (size_t)i * n * WCOLS4 + lane;

    // Each warp owns adjacent j-pairs: 1KB contiguous store burst / iter.
    #pragma unroll 2
    for (int j = 2 * wid; j < n; j += 2 * NWARPS) {
        const int4 pjj = *(const int4*)&s_feat[j];     // feats for j and j+1

        float4 acc0, acc1;
        {
            const int  x     = pi.x ^ pjj.x;
            const bool same  = (x & 0xFF)   == 0;
            const bool mente = (x & 0xFF00) == 0;
            if (!same) {
                int sym_j = (pjj.x >> 16) & 0xFF;
                int d_ch  = min(max(sym_i - sym_j + 2, 0), 4);
                acc0 = lut[(d_ch + (mente ? 5 : 0)) * WCOLS4 + lane];
            } else {
                int dres  = res_i - (pjj.y & 0xFFFF);
                int d_res = min(max(dres + 32, 0), 64);
                int d_tok = 65;
                if (dres == 0)
                    d_tok = min(max(tok_i - (pjj.y >> 16) + 32, 0), 64);
                float4 a = __ldg(&W4[d_res * WCOLS4 + lane]);
                float4 b = __ldg(&W4[(66 + d_tok) * WCOLS4 + lane]);
                acc0 = f4add(f4add(a, b), mente ? wch5e : wch5);
            }
        }
        {
            const int  x     = pi.x ^ pjj.z;
            const bool same  = (x & 0xFF)   == 0;
            const bool mente = (x & 0xFF00) == 0;
            if (!same) {
                int sym_j = (pjj.z >> 16) & 0xFF;
                int d_ch  = min(max(sym_i - sym_j + 2, 0), 4);
                acc1 = lut[(d_ch + (mente ? 5 : 0)) * WCOLS4 + lane];
            } else {
                int dres  = res_i - (pjj.w & 0xFFFF);
                int d_res = min(max(dres + 32, 0), 64);
                int d_tok = 65;
                if (dres == 0)
                    d_tok = min(max(tok_i - (pjj.w >> 16) + 32, 0), 64);
                float4 a = __ldg(&W4[d_res * WCOLS4 + lane]);
                float4 b = __ldg(&W4[(66 + d_tok) * WCOLS4 + lane]);
                acc1 = f4add(f4add(a, b), mente ? wch5e : wch5);
            }
        }

        outp[(size_t)j * WCOLS4]       = acc0;         // back-to-back 512B
        outp[(size_t)(j + 1) * WCOLS4] = acc1;         // -> 1KB burst
    }
}

extern "C" void kernel_launch(void* const* d_in, const int* in_sizes, int n_in,
                              void* d_out, int out_size) {
    const float* feats = (const float*)d_in[0];
    const float* W     = (const float*)d_in[1];
    float*       out   = (float*)d_out;

    const int n = in_sizes[0] / 10;   // 1024
    const size_t smem = (size_t)10 * 128 * sizeof(float)   // LUT
                      + (size_t)n * sizeof(int2);          // packed feats

    cudaFuncSetAttribute(relpos_kernel,
                         cudaFuncAttributeMaxDynamicSharedMemorySize, (int)smem);

    relpos_kernel<<<n, NTHREADS, smem>>>(feats, W, out, n);
}